// round 1
// baseline (speedup 1.0000x reference)
#include <cuda_runtime.h>
#include <math.h>

// Mesh: 128^3 complex (float2) = 16 MB, static device scratch (no allocs allowed).
#define NMESH 128
#define N3 (128*128*128)

__device__ float2 d_mesh[N3];
__device__ float  d_minv[9];
__device__ float  d_brec[9];
__device__ float  d_invvol;

// ---------------------------------------------------------------------------
// Setup: 3x3 inverse, reciprocal basis (2*pi*inv(cell)^T), 1/|det|
// ---------------------------------------------------------------------------
__global__ void k_setup(const float* __restrict__ cell) {
    float a = cell[0], b = cell[1], c = cell[2];
    float d = cell[3], e = cell[4], f = cell[5];
    float g = cell[6], h = cell[7], i = cell[8];
    // cofactors
    float C00 =  (e*i - f*h), C01 = -(d*i - f*g), C02 =  (d*h - e*g);
    float C10 = -(b*i - c*h), C11 =  (a*i - c*g), C12 = -(a*h - b*g);
    float C20 =  (b*f - c*e), C21 = -(a*f - c*d), C22 =  (a*e - b*d);
    float det = a*C00 + b*C01 + c*C02;
    float idet = 1.0f / det;
    // inv[r][s] = Cof[s][r] / det
    float inv[9];
    inv[0] = C00*idet; inv[1] = C10*idet; inv[2] = C20*idet;
    inv[3] = C01*idet; inv[4] = C11*idet; inv[5] = C21*idet;
    inv[6] = C02*idet; inv[7] = C12*idet; inv[8] = C22*idet;
    for (int t = 0; t < 9; t++) d_minv[t] = inv[t];
    const float TWO_PI = 6.283185307179586f;
    // Brec[r][s] = 2*pi * inv[s][r]
    for (int r = 0; r < 3; r++)
        for (int s = 0; s < 3; s++)
            d_brec[r*3+s] = TWO_PI * inv[s*3+r];
    d_invvol = 1.0f / fabsf(det);
}

// ---------------------------------------------------------------------------
// Zero mesh (16 MB) with float4 stores
// ---------------------------------------------------------------------------
__global__ void k_zero() {
    int i = blockIdx.x * blockDim.x + threadIdx.x;   // 1048576 float4s
    ((float4*)d_mesh)[i] = make_float4(0.f, 0.f, 0.f, 0.f);
}

// ---------------------------------------------------------------------------
// Order-4 (M4 / P3M) spline weights, x in [-1/2, 1/2)
// ---------------------------------------------------------------------------
__device__ __forceinline__ void spline_w4(float x, float* w) {
    float x2 = x * x, x3 = x2 * x;
    const float s = 1.0f / 48.0f;
    w[0] = ( 1.0f -  6.0f*x + 12.0f*x2 -  8.0f*x3) * s;
    w[1] = (23.0f - 30.0f*x - 12.0f*x2 + 24.0f*x3) * s;
    w[2] = (23.0f + 30.0f*x - 12.0f*x2 - 24.0f*x3) * s;
    w[3] = ( 1.0f +  6.0f*x + 12.0f*x2 +  8.0f*x3) * s;
}

__device__ __forceinline__ void atom_stencil(
    const float* __restrict__ pos, int a,
    float* wx, float* wy, float* wz, int* ix, int* iy, int* iz)
{
    float p0 = pos[3*a], p1 = pos[3*a+1], p2 = pos[3*a+2];
    float r0 = (p0*d_minv[0] + p1*d_minv[3] + p2*d_minv[6]) * 128.0f;
    float r1 = (p0*d_minv[1] + p1*d_minv[4] + p2*d_minv[7]) * 128.0f;
    float r2 = (p0*d_minv[2] + p1*d_minv[5] + p2*d_minv[8]) * 128.0f;
    int i0 = __float2int_rd(r0);
    int i1 = __float2int_rd(r1);
    int i2 = __float2int_rd(r2);
    spline_w4(r0 - (float)i0 - 0.5f, wx);
    spline_w4(r1 - (float)i1 - 0.5f, wy);
    spline_w4(r2 - (float)i2 - 0.5f, wz);
    #pragma unroll
    for (int s = 0; s < 4; s++) {
        ix[s] = (i0 + s - 1 + 128) & 127;
        iy[s] = (i1 + s - 1 + 128) & 127;
        iz[s] = (i2 + s - 1 + 128) & 127;
    }
}

// ---------------------------------------------------------------------------
// Scatter: charge * 4x4x4 spline weights -> atomicAdd into mesh real part
// ---------------------------------------------------------------------------
__global__ void k_scatter(const float* __restrict__ pos,
                          const float* __restrict__ chg, int n) {
    int a = blockIdx.x * blockDim.x + threadIdx.x;
    if (a >= n) return;
    float wx[4], wy[4], wz[4];
    int ix[4], iy[4], iz[4];
    atom_stencil(pos, a, wx, wy, wz, ix, iy, iz);
    float c = chg[a];
    #pragma unroll
    for (int i = 0; i < 4; i++) {
        float cwi = c * wx[i];
        int ox = ix[i] << 14;
        #pragma unroll
        for (int j = 0; j < 4; j++) {
            float cwij = cwi * wy[j];
            int oxy = ox + (iy[j] << 7);
            #pragma unroll
            for (int k = 0; k < 4; k++) {
                atomicAdd(&d_mesh[oxy + iz[k]].x, cwij * wz[k]);
            }
        }
    }
}

// ---------------------------------------------------------------------------
// 128-pt radix-2 Stockham FFT over one axis; 16 lines per block, 256 threads.
// MODE 0: z axis (stride 1, lines contiguous)
// MODE 1: y axis (stride 128, batch 16 contiguous z)
// MODE 2: x axis (stride 16384, batch 16 contiguous inner)
// SIGN -1: forward, +1: (unnormalized) inverse
// ---------------------------------------------------------------------------
template<int SIGN, int MODE>
__global__ void k_fft() {
    __shared__ float2 bufA[16 * 129];
    __shared__ float2 bufB[16 * 129];
    __shared__ float2 tw[64];
    int tid  = threadIdx.x;
    int tile = blockIdx.x;

    if (tid < 64) {
        float sv, cv;
        sincospif((float)SIGN * (float)tid * (1.0f / 64.0f), &sv, &cv);
        tw[tid] = make_float2(cv, sv);
    }

    int base, S;
    if (MODE == 0)      { base = tile * 2048;                               S = 1;     }
    else if (MODE == 1) { base = ((tile >> 3) << 14) + ((tile & 7) << 4);   S = 128;   }
    else                { base = tile << 4;                                 S = 16384; }

    // Load tile into shared (padded line stride 129)
    if (MODE == 0) {
        #pragma unroll
        for (int e = tid; e < 2048; e += 256) {
            int c = e >> 7, l = e & 127;
            bufA[c * 129 + l] = d_mesh[base + e];
        }
    } else {
        #pragma unroll
        for (int e = tid; e < 2048; e += 256) {
            int c = e & 15, l = e >> 4;
            bufA[c * 129 + l] = d_mesh[base + l * S + c];
        }
    }
    __syncthreads();

    float2* cur = bufA;
    float2* nxt = bufB;
    #pragma unroll
    for (int stage = 0; stage < 7; stage++) {
        int s = 1 << stage;
        #pragma unroll
        for (int u = tid; u < 1024; u += 256) {
            int c = u >> 6, t = u & 63;
            int q  = t & (s - 1);
            int p  = t >> stage;
            int sp = t - q;             // s * p
            float2 a = cur[c * 129 + t];
            float2 b = cur[c * 129 + t + 64];
            float2 w = tw[(p << stage) & 63];
            float2 su = make_float2(a.x + b.x, a.y + b.y);
            float2 df = make_float2(a.x - b.x, a.y - b.y);
            float2 wd = make_float2(df.x * w.x - df.y * w.y,
                                    df.x * w.y + df.y * w.x);
            nxt[c * 129 + t + sp]     = su;
            nxt[c * 129 + t + sp + s] = wd;
        }
        float2* tmp = cur; cur = nxt; nxt = tmp;
        __syncthreads();
    }

    // Store (result is in cur)
    if (MODE == 0) {
        #pragma unroll
        for (int e = tid; e < 2048; e += 256) {
            int c = e >> 7, l = e & 127;
            d_mesh[base + e] = cur[c * 129 + l];
        }
    } else {
        #pragma unroll
        for (int e = tid; e < 2048; e += 256) {
            int c = e & 15, l = e >> 4;
            d_mesh[base + l * S + c] = cur[c * 129 + l];
        }
    }
}

// ---------------------------------------------------------------------------
// Multiply by G(k)/V in k-space. G(0)=0.
// ---------------------------------------------------------------------------
__global__ void k_gmul() {
    int idx = blockIdx.x * blockDim.x + threadIdx.x;   // 2M
    int kk = idx & 127;
    int jj = (idx >> 7) & 127;
    int ii = idx >> 14;
    float mi = (float)(ii - ((ii >= 64) ? 128 : 0));
    float mj = (float)(jj - ((jj >= 64) ? 128 : 0));
    float mk = (float)(kk - ((kk >= 64) ? 128 : 0));
    float kx = mi * d_brec[0] + mj * d_brec[3] + mk * d_brec[6];
    float ky = mi * d_brec[1] + mj * d_brec[4] + mk * d_brec[7];
    float kz = mi * d_brec[2] + mj * d_brec[5] + mk * d_brec[8];
    float ksq = kx * kx + ky * ky + kz * kz;
    float g = 0.0f;
    if (ksq != 0.0f)
        g = 12.566370614359172f / ksq * expf(-0.5f * ksq) * d_invvol;
    float2 v = d_mesh[idx];
    v.x *= g; v.y *= g;
    d_mesh[idx] = v;
}

// ---------------------------------------------------------------------------
// Gather: potential at atoms = sum(w * mesh.real) - q * sqrt(2/pi)/sigma
// ---------------------------------------------------------------------------
__global__ void k_gather(const float* __restrict__ pos,
                         const float* __restrict__ chg,
                         float* __restrict__ out, int n) {
    int a = blockIdx.x * blockDim.x + threadIdx.x;
    if (a >= n) return;
    float wx[4], wy[4], wz[4];
    int ix[4], iy[4], iz[4];
    atom_stencil(pos, a, wx, wy, wz, ix, iy, iz);
    float sum = 0.0f;
    #pragma unroll
    for (int i = 0; i < 4; i++) {
        float wi = wx[i];
        int ox = ix[i] << 14;
        #pragma unroll
        for (int j = 0; j < 4; j++) {
            float wij = wi * wy[j];
            int oxy = ox + (iy[j] << 7);
            float acc = 0.0f;
            #pragma unroll
            for (int k = 0; k < 4; k++)
                acc += wz[k] * d_mesh[oxy + iz[k]].x;
            sum += wij * acc;
        }
    }
    out[a] = sum - chg[a] * 0.7978845608028654f;
}

// ---------------------------------------------------------------------------
extern "C" void kernel_launch(void* const* d_in, const int* in_sizes, int n_in,
                              void* d_out, int out_size) {
    const float* cell = (const float*)d_in[0];
    const float* pos  = (const float*)d_in[1];
    const float* chg  = (const float*)d_in[2];
    float* out = (float*)d_out;
    int n = in_sizes[2];                 // 200000 charges (shape (n,1))

    k_setup<<<1, 1>>>(cell);
    k_zero<<<4096, 256>>>();             // 1048576 float4s

    int ab = (n + 255) / 256;
    k_scatter<<<ab, 256>>>(pos, chg, n);

    k_fft<-1, 0><<<1024, 256>>>();       // forward z
    k_fft<-1, 1><<<1024, 256>>>();       // forward y
    k_fft<-1, 2><<<1024, 256>>>();       // forward x
    k_gmul<<<N3 / 256, 256>>>();
    k_fft< 1, 2><<<1024, 256>>>();       // inverse x
    k_fft< 1, 1><<<1024, 256>>>();       // inverse y
    k_fft< 1, 0><<<1024, 256>>>();       // inverse z

    k_gather<<<ab, 256>>>(pos, chg, out, n);
}

// round 2
// speedup vs baseline: 1.1854x; 1.1854x over previous
#include <cuda_runtime.h>
#include <math.h>

#define N3 (128*128*128)

__device__ float2 d_mesh[N3];   // complex work mesh (16 MB)
__device__ float  d_rho[N3];    // dense real mesh for scatter/gather (8 MB)
__device__ float  d_minv[9];
__device__ float  d_brec[9];
__device__ float  d_invvol;

// ---------------------------------------------------------------------------
__global__ void k_setup(const float* __restrict__ cell) {
    float a = cell[0], b = cell[1], c = cell[2];
    float d = cell[3], e = cell[4], f = cell[5];
    float g = cell[6], h = cell[7], i = cell[8];
    float C00 =  (e*i - f*h), C01 = -(d*i - f*g), C02 =  (d*h - e*g);
    float C10 = -(b*i - c*h), C11 =  (a*i - c*g), C12 = -(a*h - b*g);
    float C20 =  (b*f - c*e), C21 = -(a*f - c*d), C22 =  (a*e - b*d);
    float det = a*C00 + b*C01 + c*C02;
    float idet = 1.0f / det;
    float inv[9];
    inv[0] = C00*idet; inv[1] = C10*idet; inv[2] = C20*idet;
    inv[3] = C01*idet; inv[4] = C11*idet; inv[5] = C21*idet;
    inv[6] = C02*idet; inv[7] = C12*idet; inv[8] = C22*idet;
    for (int t = 0; t < 9; t++) d_minv[t] = inv[t];
    const float TWO_PI = 6.283185307179586f;
    for (int r = 0; r < 3; r++)
        for (int s = 0; s < 3; s++)
            d_brec[r*3+s] = TWO_PI * inv[s*3+r];
    d_invvol = 1.0f / fabsf(det);
}

__global__ void k_zero() {
    int i = blockIdx.x * blockDim.x + threadIdx.x;   // 524288 float4s (8 MB)
    ((float4*)d_rho)[i] = make_float4(0.f, 0.f, 0.f, 0.f);
}

// ---------------------------------------------------------------------------
// complex helpers
// ---------------------------------------------------------------------------
__device__ __forceinline__ float2 cadd(float2 a, float2 b){ return make_float2(a.x+b.x, a.y+b.y); }
__device__ __forceinline__ float2 csub(float2 a, float2 b){ return make_float2(a.x-b.x, a.y-b.y); }
__device__ __forceinline__ float2 cmul(float2 a, float2 w){ return make_float2(a.x*w.x-a.y*w.y, a.x*w.y+a.y*w.x); }

// ---------------------------------------------------------------------------
// Radix-4 Stockham stage over 16 lines of 128 (padded stride 129).
// tw[j] = exp(-2*pi*i*j/128); CONJ=1 conjugates (inverse transform).
// 32 butterflies per line * 16 lines = 512 items, 256 threads.
// ---------------------------------------------------------------------------
template<int CONJ, int S>
__device__ __forceinline__ void r4_stage(const float2* __restrict__ cur,
                                         float2* __restrict__ nxt,
                                         const float2* __restrict__ tw, int tid) {
    #pragma unroll
    for (int u = tid; u < 512; u += 256) {
        int c = u >> 5, t = u & 31;
        int off = c * 129;
        int q  = t & (S - 1);
        int sp = t - q;                       // S * p
        float2 a0 = cur[off + t];
        float2 a1 = cur[off + t + 32];
        float2 a2 = cur[off + t + 64];
        float2 a3 = cur[off + t + 96];
        float2 t02 = cadd(a0, a2), d02 = csub(a0, a2);
        float2 t13 = cadd(a1, a3), d13 = csub(a1, a3);
        float2 y0 = cadd(t02, t13);
        float2 y2 = csub(t02, t13);
        float2 jd;                             // sigma*i*d13, sigma = CONJ? +1 : -1
        if (CONJ) jd = make_float2(-d13.y,  d13.x);
        else      jd = make_float2( d13.y, -d13.x);
        float2 y1 = cadd(d02, jd);
        float2 y3 = csub(d02, jd);
        float2 w1 = tw[sp], w2 = tw[2*sp], w3 = tw[3*sp];
        if (CONJ) { w1.y = -w1.y; w2.y = -w2.y; w3.y = -w3.y; }
        int o = off + t + 3*sp;                // q + 4*S*p
        nxt[o]       = y0;
        nxt[o + S]   = cmul(y1, w1);
        nxt[o + 2*S] = cmul(y2, w2);
        nxt[o + 3*S] = cmul(y3, w3);
    }
}

template<int CONJ>
__device__ __forceinline__ void fft_r4_stages(float2* A, float2* B,
                                              const float2* tw, int tid) {
    r4_stage<CONJ, 1 >(A, B, tw, tid); __syncthreads();
    r4_stage<CONJ, 4 >(B, A, tw, tid); __syncthreads();
    r4_stage<CONJ, 16>(A, B, tw, tid); __syncthreads();
    // pre-final-radix-2 result is in B; caller does twiddle-free r2.
}

__device__ __forceinline__ void init_tw(float2* tw, int tid) {
    if (tid < 128) {
        float s, c;
        sincospif((float)tid * (1.0f / 64.0f), &s, &c);
        tw[tid] = make_float2(c, -s);
    }
}

// ---------------------------------------------------------------------------
// z forward: real d_rho -> complex d_mesh (contiguous lines)
// ---------------------------------------------------------------------------
__global__ void k_fft_z_fwd() {
    __shared__ float2 bufA[16 * 129];
    __shared__ float2 bufB[16 * 129];
    __shared__ float2 tw[128];
    int tid = threadIdx.x;
    int base = blockIdx.x * 2048;
    init_tw(tw, tid);
    #pragma unroll
    for (int e = tid; e < 2048; e += 256) {
        int c = e >> 7, l = e & 127;
        bufA[c * 129 + l] = make_float2(d_rho[base + e], 0.0f);
    }
    __syncthreads();
    fft_r4_stages<0>(bufA, bufB, tw, tid);
    #pragma unroll
    for (int e = tid; e < 1024; e += 256) {
        int c = e >> 6, l = e & 63;
        float2 a = bufB[c * 129 + l], b = bufB[c * 129 + l + 64];
        d_mesh[base + c * 128 + l]      = cadd(a, b);
        d_mesh[base + c * 128 + l + 64] = csub(a, b);
    }
}

// ---------------------------------------------------------------------------
// z inverse: complex d_mesh -> real d_rho
// ---------------------------------------------------------------------------
__global__ void k_fft_z_inv() {
    __shared__ float2 bufA[16 * 129];
    __shared__ float2 bufB[16 * 129];
    __shared__ float2 tw[128];
    int tid = threadIdx.x;
    int base = blockIdx.x * 2048;
    init_tw(tw, tid);
    #pragma unroll
    for (int e = tid; e < 2048; e += 256) {
        int c = e >> 7, l = e & 127;
        bufA[c * 129 + l] = d_mesh[base + e];
    }
    __syncthreads();
    fft_r4_stages<1>(bufA, bufB, tw, tid);
    #pragma unroll
    for (int e = tid; e < 1024; e += 256) {
        int c = e >> 6, l = e & 63;
        float2 a = bufB[c * 129 + l], b = bufB[c * 129 + l + 64];
        d_rho[base + c * 128 + l]      = a.x + b.x;
        d_rho[base + c * 128 + l + 64] = a.x - b.x;
    }
}

// ---------------------------------------------------------------------------
// y pass (stride 128), complex<->complex. CONJ=0 forward, 1 inverse.
// tile covers: fixed x (tile>>3), z-chunk of 16 (tile&7), all y.
// ---------------------------------------------------------------------------
template<int CONJ>
__global__ void k_fft_y() {
    __shared__ float2 bufA[16 * 129];
    __shared__ float2 bufB[16 * 129];
    __shared__ float2 tw[128];
    int tid = threadIdx.x;
    int tile = blockIdx.x;
    int base = ((tile >> 3) << 14) + ((tile & 7) << 4);
    init_tw(tw, tid);
    #pragma unroll
    for (int e = tid; e < 2048; e += 256) {
        int c = e & 15, l = e >> 4;
        bufA[c * 129 + l] = d_mesh[base + l * 128 + c];
    }
    __syncthreads();
    fft_r4_stages<CONJ>(bufA, bufB, tw, tid);
    #pragma unroll
    for (int e = tid; e < 1024; e += 256) {
        int c = e & 15, l = e >> 4;            // l in [0,64)
        float2 a = bufB[c * 129 + l], b = bufB[c * 129 + l + 64];
        d_mesh[base + l * 128 + c]        = cadd(a, b);
        d_mesh[base + (l + 64) * 128 + c] = csub(a, b);
    }
}

// ---------------------------------------------------------------------------
// Fused x pass: forward FFT along x, multiply by G(k)/V, inverse FFT along x.
// tile covers (y,z)-chunk of 16 inner elements, all x (stride 16384).
// ---------------------------------------------------------------------------
__global__ void k_fft_x_gmul() {
    __shared__ float2 bufA[16 * 129];
    __shared__ float2 bufB[16 * 129];
    __shared__ float2 tw[128];
    int tid = threadIdx.x;
    int base = blockIdx.x << 4;
    init_tw(tw, tid);
    #pragma unroll
    for (int e = tid; e < 2048; e += 256) {
        int c = e & 15, l = e >> 4;
        bufA[c * 129 + l] = d_mesh[base + l * 16384 + c];
    }
    __syncthreads();
    // forward
    fft_r4_stages<0>(bufA, bufB, tw, tid);
    // final radix-2 into A (full forward spectrum, natural order)
    #pragma unroll
    for (int e = tid; e < 1024; e += 256) {
        int c = e >> 6, t = e & 63;
        float2 a = bufB[c * 129 + t], b = bufB[c * 129 + t + 64];
        bufA[c * 129 + t]      = cadd(a, b);
        bufA[c * 129 + t + 64] = csub(a, b);
    }
    __syncthreads();
    // multiply by G(k)/V
    float b0x = d_brec[0], b0y = d_brec[1], b0z = d_brec[2];
    float b1x = d_brec[3], b1y = d_brec[4], b1z = d_brec[5];
    float b2x = d_brec[6], b2y = d_brec[7], b2z = d_brec[8];
    float ivol = d_invvol;
    #pragma unroll
    for (int e = tid; e < 2048; e += 256) {
        int c = e >> 7, x = e & 127;
        int gp = base + c;
        int y = gp >> 7, z = gp & 127;
        float mi = (float)(x - ((x >= 64) ? 128 : 0));
        float mj = (float)(y - ((y >= 64) ? 128 : 0));
        float mk = (float)(z - ((z >= 64) ? 128 : 0));
        float kx = mi * b0x + mj * b1x + mk * b2x;
        float ky = mi * b0y + mj * b1y + mk * b2y;
        float kz = mi * b0z + mj * b1z + mk * b2z;
        float ksq = kx * kx + ky * ky + kz * kz;
        float g = 0.0f;
        if (ksq != 0.0f)
            g = 12.566370614359172f / ksq * expf(-0.5f * ksq) * ivol;
        float2 v = bufA[c * 129 + x];
        v.x *= g; v.y *= g;
        bufA[c * 129 + x] = v;
    }
    __syncthreads();
    // inverse
    fft_r4_stages<1>(bufA, bufB, tw, tid);
    #pragma unroll
    for (int e = tid; e < 1024; e += 256) {
        int c = e & 15, l = e >> 4;
        float2 a = bufB[c * 129 + l], b = bufB[c * 129 + l + 64];
        d_mesh[base + l * 16384 + c]        = cadd(a, b);
        d_mesh[base + (l + 64) * 16384 + c] = csub(a, b);
    }
}

// ---------------------------------------------------------------------------
// Order-4 (M4 / P3M) spline weights
// ---------------------------------------------------------------------------
__device__ __forceinline__ void spline_w4(float x, float* w) {
    float x2 = x * x, x3 = x2 * x;
    const float s = 1.0f / 48.0f;
    w[0] = ( 1.0f -  6.0f*x + 12.0f*x2 -  8.0f*x3) * s;
    w[1] = (23.0f - 30.0f*x - 12.0f*x2 + 24.0f*x3) * s;
    w[2] = (23.0f + 30.0f*x - 12.0f*x2 - 24.0f*x3) * s;
    w[3] = ( 1.0f +  6.0f*x + 12.0f*x2 +  8.0f*x3) * s;
}

__device__ __forceinline__ void atom_stencil(
    const float* __restrict__ pos, int a,
    float* wx, float* wy, float* wz, int* ix, int* iy, int* iz)
{
    float p0 = pos[3*a], p1 = pos[3*a+1], p2 = pos[3*a+2];
    float r0 = (p0*d_minv[0] + p1*d_minv[3] + p2*d_minv[6]) * 128.0f;
    float r1 = (p0*d_minv[1] + p1*d_minv[4] + p2*d_minv[7]) * 128.0f;
    float r2 = (p0*d_minv[2] + p1*d_minv[5] + p2*d_minv[8]) * 128.0f;
    int i0 = __float2int_rd(r0);
    int i1 = __float2int_rd(r1);
    int i2 = __float2int_rd(r2);
    spline_w4(r0 - (float)i0 - 0.5f, wx);
    spline_w4(r1 - (float)i1 - 0.5f, wy);
    spline_w4(r2 - (float)i2 - 0.5f, wz);
    #pragma unroll
    for (int s = 0; s < 4; s++) {
        ix[s] = (i0 + s - 1 + 128) & 127;
        iy[s] = (i1 + s - 1 + 128) & 127;
        iz[s] = (i2 + s - 1 + 128) & 127;
    }
}

__global__ void k_scatter(const float* __restrict__ pos,
                          const float* __restrict__ chg, int n) {
    int a = blockIdx.x * blockDim.x + threadIdx.x;
    if (a >= n) return;
    float wx[4], wy[4], wz[4];
    int ix[4], iy[4], iz[4];
    atom_stencil(pos, a, wx, wy, wz, ix, iy, iz);
    float c = chg[a];
    #pragma unroll
    for (int i = 0; i < 4; i++) {
        float cwi = c * wx[i];
        int ox = ix[i] << 14;
        #pragma unroll
        for (int j = 0; j < 4; j++) {
            float cwij = cwi * wy[j];
            int oxy = ox + (iy[j] << 7);
            #pragma unroll
            for (int k = 0; k < 4; k++)
                atomicAdd(&d_rho[oxy + iz[k]], cwij * wz[k]);
        }
    }
}

__global__ void k_gather(const float* __restrict__ pos,
                         const float* __restrict__ chg,
                         float* __restrict__ out, int n) {
    int a = blockIdx.x * blockDim.x + threadIdx.x;
    if (a >= n) return;
    float wx[4], wy[4], wz[4];
    int ix[4], iy[4], iz[4];
    atom_stencil(pos, a, wx, wy, wz, ix, iy, iz);
    float sum = 0.0f;
    #pragma unroll
    for (int i = 0; i < 4; i++) {
        float wi = wx[i];
        int ox = ix[i] << 14;
        #pragma unroll
        for (int j = 0; j < 4; j++) {
            float wij = wi * wy[j];
            int oxy = ox + (iy[j] << 7);
            float acc = 0.0f;
            #pragma unroll
            for (int k = 0; k < 4; k++)
                acc += wz[k] * d_rho[oxy + iz[k]];
            sum += wij * acc;
        }
    }
    out[a] = sum - chg[a] * 0.7978845608028654f;
}

// ---------------------------------------------------------------------------
extern "C" void kernel_launch(void* const* d_in, const int* in_sizes, int n_in,
                              void* d_out, int out_size) {
    const float* cell = (const float*)d_in[0];
    const float* pos  = (const float*)d_in[1];
    const float* chg  = (const float*)d_in[2];
    float* out = (float*)d_out;
    int n = in_sizes[2];

    k_setup<<<1, 1>>>(cell);
    k_zero<<<2048, 256>>>();

    int ab = (n + 255) / 256;
    k_scatter<<<ab, 256>>>(pos, chg, n);

    k_fft_z_fwd<<<1024, 256>>>();
    k_fft_y<0><<<1024, 256>>>();
    k_fft_x_gmul<<<1024, 256>>>();
    k_fft_y<1><<<1024, 256>>>();
    k_fft_z_inv<<<1024, 256>>>();

    k_gather<<<ab, 256>>>(pos, chg, out, n);
}

// round 3
// speedup vs baseline: 1.7542x; 1.4799x over previous
#include <cuda_runtime.h>
#include <math.h>

#define N3 (128*128*128)
#define NZH 65                       // Hermitian half length along z
#define NLINES (128*128)             // 16384 real z-lines
#define KLINES (128*65)              // 8320 k-space lines for y/x passes

__device__ float2 d_kmesh[128*128*NZH];  // half-spectrum mesh (8.5 MB)
__device__ float  d_rho[N3];             // dense real mesh (8 MB)
__device__ float  d_minv[9];
__device__ float  d_brec[9];
__device__ float  d_invvol;

// ---------------------------------------------------------------------------
__global__ void k_setup(const float* __restrict__ cell) {
    float a = cell[0], b = cell[1], c = cell[2];
    float d = cell[3], e = cell[4], f = cell[5];
    float g = cell[6], h = cell[7], i = cell[8];
    float C00 =  (e*i - f*h), C01 = -(d*i - f*g), C02 =  (d*h - e*g);
    float C10 = -(b*i - c*h), C11 =  (a*i - c*g), C12 = -(a*h - b*g);
    float C20 =  (b*f - c*e), C21 = -(a*f - c*d), C22 =  (a*e - b*d);
    float det = a*C00 + b*C01 + c*C02;
    float idet = 1.0f / det;
    float inv[9];
    inv[0] = C00*idet; inv[1] = C10*idet; inv[2] = C20*idet;
    inv[3] = C01*idet; inv[4] = C11*idet; inv[5] = C21*idet;
    inv[6] = C02*idet; inv[7] = C12*idet; inv[8] = C22*idet;
    for (int t = 0; t < 9; t++) d_minv[t] = inv[t];
    const float TWO_PI = 6.283185307179586f;
    for (int r = 0; r < 3; r++)
        for (int s = 0; s < 3; s++)
            d_brec[r*3+s] = TWO_PI * inv[s*3+r];
    d_invvol = 1.0f / fabsf(det);
}

__global__ void k_zero() {
    int i = blockIdx.x * blockDim.x + threadIdx.x;   // 524288 float4s (8 MB)
    ((float4*)d_rho)[i] = make_float4(0.f, 0.f, 0.f, 0.f);
}

// ---------------------------------------------------------------------------
__device__ __forceinline__ float2 cadd(float2 a, float2 b){ return make_float2(a.x+b.x, a.y+b.y); }
__device__ __forceinline__ float2 csub(float2 a, float2 b){ return make_float2(a.x-b.x, a.y-b.y); }
__device__ __forceinline__ float2 cmul(float2 a, float2 w){ return make_float2(a.x*w.x-a.y*w.y, a.x*w.y+a.y*w.x); }

// Radix-4 Stockham stage over 16 lines of 128 (padded stride 129).
template<int CONJ, int S>
__device__ __forceinline__ void r4_stage(const float2* __restrict__ cur,
                                         float2* __restrict__ nxt,
                                         const float2* __restrict__ tw, int tid) {
    #pragma unroll
    for (int u = tid; u < 512; u += 256) {
        int c = u >> 5, t = u & 31;
        int off = c * 129;
        int q  = t & (S - 1);
        int sp = t - q;
        float2 a0 = cur[off + t];
        float2 a1 = cur[off + t + 32];
        float2 a2 = cur[off + t + 64];
        float2 a3 = cur[off + t + 96];
        float2 t02 = cadd(a0, a2), d02 = csub(a0, a2);
        float2 t13 = cadd(a1, a3), d13 = csub(a1, a3);
        float2 y0 = cadd(t02, t13);
        float2 y2 = csub(t02, t13);
        float2 jd;
        if (CONJ) jd = make_float2(-d13.y,  d13.x);
        else      jd = make_float2( d13.y, -d13.x);
        float2 y1 = cadd(d02, jd);
        float2 y3 = csub(d02, jd);
        float2 w1 = tw[sp], w2 = tw[2*sp], w3 = tw[3*sp];
        if (CONJ) { w1.y = -w1.y; w2.y = -w2.y; w3.y = -w3.y; }
        int o = off + t + 3*sp;
        nxt[o]       = y0;
        nxt[o + S]   = cmul(y1, w1);
        nxt[o + 2*S] = cmul(y2, w2);
        nxt[o + 3*S] = cmul(y3, w3);
    }
}

template<int CONJ>
__device__ __forceinline__ void fft_r4_stages(float2* A, float2* B,
                                              const float2* tw, int tid) {
    r4_stage<CONJ, 1 >(A, B, tw, tid); __syncthreads();
    r4_stage<CONJ, 4 >(B, A, tw, tid); __syncthreads();
    r4_stage<CONJ, 16>(A, B, tw, tid); __syncthreads();
    // result (pre final radix-2) in B
}

// twiddle-free final radix-2, shared -> shared (full natural-order spectrum)
__device__ __forceinline__ void r2_final_shared(const float2* __restrict__ src,
                                                float2* __restrict__ dst, int tid) {
    #pragma unroll
    for (int e = tid; e < 1024; e += 256) {
        int c = e >> 6, t = e & 63;
        float2 a = src[c * 129 + t], b = src[c * 129 + t + 64];
        dst[c * 129 + t]      = cadd(a, b);
        dst[c * 129 + t + 64] = csub(a, b);
    }
}

__device__ __forceinline__ void init_tw(float2* tw, int tid) {
    if (tid < 128) {
        float s, c;
        sincospif((float)tid * (1.0f / 64.0f), &s, &c);
        tw[tid] = make_float2(c, -s);
    }
}

// ---------------------------------------------------------------------------
// z forward r2c (two-for-one): 32 real lines -> 32 half-spectrum lines / block
// ---------------------------------------------------------------------------
__global__ void k_fft_z_fwd() {
    __shared__ float2 bufA[16 * 129];
    __shared__ float2 bufB[16 * 129];
    __shared__ float2 tw[128];
    int tid = threadIdx.x;
    int rl0 = blockIdx.x * 32;                 // first real line
    init_tw(tw, tid);
    const float* rp = d_rho + rl0 * 128;
    #pragma unroll
    for (int e = tid; e < 2048; e += 256) {
        int c = e >> 7, l = e & 127;
        bufA[c * 129 + l] = make_float2(rp[(2*c) * 128 + l], rp[(2*c+1) * 128 + l]);
    }
    __syncthreads();
    fft_r4_stages<0>(bufA, bufB, tw, tid);
    r2_final_shared(bufB, bufA, tid);
    __syncthreads();
    // unpack: real line (rl0+2c) -> A_k, (rl0+2c+1) -> B_k
    #pragma unroll
    for (int e = tid; e < 32 * NZH; e += 256) {
        int rl = e / NZH, k = e - rl * NZH;
        int c = rl >> 1;
        float2 Ck = bufA[c * 129 + k];
        float2 Cm = bufA[c * 129 + ((128 - k) & 127)];
        float2 v;
        if ((rl & 1) == 0)
            v = make_float2(0.5f * (Ck.x + Cm.x), 0.5f * (Ck.y - Cm.y));
        else
            v = make_float2(0.5f * (Ck.y + Cm.y), -0.5f * (Ck.x - Cm.x));
        d_kmesh[(rl0 + rl) * NZH + k] = v;
    }
}

// ---------------------------------------------------------------------------
// z inverse c2r (two-for-one): 32 half-spectrum lines -> 32 real lines / block
// ---------------------------------------------------------------------------
__global__ void k_fft_z_inv() {
    __shared__ float2 bufA[16 * 129];
    __shared__ float2 bufB[16 * 129];
    __shared__ float2 tw[128];
    int tid = threadIdx.x;
    int rl0 = blockIdx.x * 32;
    init_tw(tw, tid);
    #pragma unroll
    for (int e = tid; e < 16 * NZH; e += 256) {
        int c = e / NZH, k = e - c * NZH;
        float2 A = d_kmesh[(rl0 + 2*c)   * NZH + k];
        float2 B = d_kmesh[(rl0 + 2*c+1) * NZH + k];
        bufA[c * 129 + k] = make_float2(A.x - B.y, A.y + B.x);
        if (k >= 1 && k <= 63)
            bufA[c * 129 + 128 - k] = make_float2(A.x + B.y, B.x - A.y);
    }
    __syncthreads();
    fft_r4_stages<1>(bufA, bufB, tw, tid);
    float* rp = d_rho + rl0 * 128;
    #pragma unroll
    for (int e = tid; e < 1024; e += 256) {
        int c = e >> 6, l = e & 63;
        float2 a = bufB[c * 129 + l], b = bufB[c * 129 + l + 64];
        float2 su = cadd(a, b), df = csub(a, b);
        rp[(2*c) * 128 + l]        = su.x;
        rp[(2*c+1) * 128 + l]      = su.y;
        rp[(2*c) * 128 + l + 64]   = df.x;
        rp[(2*c+1) * 128 + l + 64] = df.y;
    }
}

// ---------------------------------------------------------------------------
// y pass: lines (x, kz) = L, elements at x*8320 + y*65 + kz.  520 blocks.
// ---------------------------------------------------------------------------
template<int CONJ>
__global__ void k_fft_y() {
    __shared__ float2 bufA[16 * 129];
    __shared__ float2 bufB[16 * 129];
    __shared__ float2 tw[128];
    __shared__ int lineBase[16];
    int tid = threadIdx.x;
    init_tw(tw, tid);
    if (tid < 16) {
        int L = blockIdx.x * 16 + tid;
        int x = L / NZH, kz = L - x * NZH;
        lineBase[tid] = x * (128 * NZH) + kz;
    }
    __syncthreads();
    #pragma unroll
    for (int e = tid; e < 2048; e += 256) {
        int c = e & 15, l = e >> 4;
        bufA[c * 129 + l] = d_kmesh[lineBase[c] + l * NZH];
    }
    __syncthreads();
    fft_r4_stages<CONJ>(bufA, bufB, tw, tid);
    #pragma unroll
    for (int e = tid; e < 1024; e += 256) {
        int c = e & 15, l = e >> 4;
        float2 a = bufB[c * 129 + l], b = bufB[c * 129 + l + 64];
        d_kmesh[lineBase[c] + l * NZH]        = cadd(a, b);
        d_kmesh[lineBase[c] + (l + 64) * NZH] = csub(a, b);
    }
}

// ---------------------------------------------------------------------------
// Fused x pass: fwd FFT along x, G(k)/V multiply, inv FFT along x. 520 blocks.
// lines L = y*65 + kz, elements at x*8320 + L.
// ---------------------------------------------------------------------------
__global__ void k_fft_x_gmul() {
    __shared__ float2 bufA[16 * 129];
    __shared__ float2 bufB[16 * 129];
    __shared__ float2 tw[128];
    __shared__ float mjv[16], mkv[16];
    int tid = threadIdx.x;
    int L0 = blockIdx.x * 16;
    init_tw(tw, tid);
    if (tid < 16) {
        int L = L0 + tid;
        int y = L / NZH, kz = L - y * NZH;
        mjv[tid] = (float)(y - ((y >= 64) ? 128 : 0));
        mkv[tid] = (float)kz;
    }
    __syncthreads();
    #pragma unroll
    for (int e = tid; e < 2048; e += 256) {
        int c = e & 15, l = e >> 4;
        bufA[c * 129 + l] = d_kmesh[L0 + c + l * KLINES];
    }
    __syncthreads();
    fft_r4_stages<0>(bufA, bufB, tw, tid);
    r2_final_shared(bufB, bufA, tid);
    __syncthreads();
    // G(k)/V
    float b0x = d_brec[0], b0y = d_brec[1], b0z = d_brec[2];
    float b1x = d_brec[3], b1y = d_brec[4], b1z = d_brec[5];
    float b2x = d_brec[6], b2y = d_brec[7], b2z = d_brec[8];
    float ivol = d_invvol;
    #pragma unroll
    for (int e = tid; e < 2048; e += 256) {
        int c = e >> 7, xk = e & 127;
        float mi = (float)(xk - ((xk >= 64) ? 128 : 0));
        float mj = mjv[c], mk = mkv[c];
        float kx = mi * b0x + mj * b1x + mk * b2x;
        float ky = mi * b0y + mj * b1y + mk * b2y;
        float kz = mi * b0z + mj * b1z + mk * b2z;
        float ksq = kx * kx + ky * ky + kz * kz;
        float g = 0.0f;
        if (ksq != 0.0f)
            g = 12.566370614359172f / ksq * expf(-0.5f * ksq) * ivol;
        float2 v = bufA[c * 129 + xk];
        v.x *= g; v.y *= g;
        bufA[c * 129 + xk] = v;
    }
    __syncthreads();
    fft_r4_stages<1>(bufA, bufB, tw, tid);
    #pragma unroll
    for (int e = tid; e < 1024; e += 256) {
        int c = e & 15, l = e >> 4;
        float2 a = bufB[c * 129 + l], b = bufB[c * 129 + l + 64];
        d_kmesh[L0 + c + l * KLINES]        = cadd(a, b);
        d_kmesh[L0 + c + (l + 64) * KLINES] = csub(a, b);
    }
}

// ---------------------------------------------------------------------------
// spline weights + stencil
// ---------------------------------------------------------------------------
__device__ __forceinline__ void spline_w4(float x, float* w) {
    float x2 = x * x, x3 = x2 * x;
    const float s = 1.0f / 48.0f;
    w[0] = ( 1.0f -  6.0f*x + 12.0f*x2 -  8.0f*x3) * s;
    w[1] = (23.0f - 30.0f*x - 12.0f*x2 + 24.0f*x3) * s;
    w[2] = (23.0f + 30.0f*x - 12.0f*x2 - 24.0f*x3) * s;
    w[3] = ( 1.0f +  6.0f*x + 12.0f*x2 +  8.0f*x3) * s;
}

// returns raw floor indices; x/y stencils pre-masked
__device__ __forceinline__ int atom_stencil(
    const float* __restrict__ pos, int a,
    float* wx, float* wy, float* wz, int* ix, int* iy)
{
    float p0 = pos[3*a], p1 = pos[3*a+1], p2 = pos[3*a+2];
    float r0 = (p0*d_minv[0] + p1*d_minv[3] + p2*d_minv[6]) * 128.0f;
    float r1 = (p0*d_minv[1] + p1*d_minv[4] + p2*d_minv[7]) * 128.0f;
    float r2 = (p0*d_minv[2] + p1*d_minv[5] + p2*d_minv[8]) * 128.0f;
    int i0 = __float2int_rd(r0);
    int i1 = __float2int_rd(r1);
    int i2 = __float2int_rd(r2);
    spline_w4(r0 - (float)i0 - 0.5f, wx);
    spline_w4(r1 - (float)i1 - 0.5f, wy);
    spline_w4(r2 - (float)i2 - 0.5f, wz);
    #pragma unroll
    for (int s = 0; s < 4; s++) {
        ix[s] = (i0 + s - 1 + 128) & 127;
        iy[s] = (i1 + s - 1 + 128) & 127;
    }
    return i2;
}

__device__ __forceinline__ void pad_quads(const float* wz, int off,
                                          float* q0, float* q1) {
    switch (off) {
    case 0: q0[0]=wz[0]; q0[1]=wz[1]; q0[2]=wz[2]; q0[3]=wz[3]; break;
    case 1: q0[1]=wz[0]; q0[2]=wz[1]; q0[3]=wz[2]; q1[0]=wz[3]; break;
    case 2: q0[2]=wz[0]; q0[3]=wz[1]; q1[0]=wz[2]; q1[1]=wz[3]; break;
    default:q0[3]=wz[0]; q1[0]=wz[1]; q1[1]=wz[2]; q1[2]=wz[3]; break;
    }
}

__device__ __forceinline__ void red4(float* p, float a, float b, float c, float d) {
    asm volatile("red.global.add.v4.f32 [%0], {%1, %2, %3, %4};"
                 :: "l"(p), "f"(a), "f"(b), "f"(c), "f"(d) : "memory");
}

// ---------------------------------------------------------------------------
__global__ void k_scatter(const float* __restrict__ pos,
                          const float* __restrict__ chg, int n) {
    int a = blockIdx.x * blockDim.x + threadIdx.x;
    if (a >= n) return;
    float wx[4], wy[4], wz[4];
    int ix[4], iy[4];
    int i2 = atom_stencil(pos, a, wx, wy, wz, ix, iy);
    float c = chg[a];
    int zlo = i2 - 1;
    if (zlo >= 0 && zlo <= 124) {
        int Q0 = zlo & ~3, off = zlo & 3;
        float q0[4] = {0,0,0,0}, q1[4] = {0,0,0,0};
        pad_quads(wz, off, q0, q1);
        #pragma unroll
        for (int i = 0; i < 4; i++) {
            float cwi = c * wx[i];
            int ox = ix[i] << 14;
            #pragma unroll
            for (int j = 0; j < 4; j++) {
                float s = cwi * wy[j];
                float* p = &d_rho[ox + (iy[j] << 7) + Q0];
                red4(p, s*q0[0], s*q0[1], s*q0[2], s*q0[3]);
                if (off) red4(p + 4, s*q1[0], s*q1[1], s*q1[2], s*q1[3]);
            }
        }
    } else {
        int iz[4];
        #pragma unroll
        for (int s = 0; s < 4; s++) iz[s] = (zlo + s + 128) & 127;
        #pragma unroll
        for (int i = 0; i < 4; i++) {
            float cwi = c * wx[i];
            int ox = ix[i] << 14;
            #pragma unroll
            for (int j = 0; j < 4; j++) {
                float cwij = cwi * wy[j];
                int oxy = ox + (iy[j] << 7);
                #pragma unroll
                for (int k = 0; k < 4; k++)
                    atomicAdd(&d_rho[oxy + iz[k]], cwij * wz[k]);
            }
        }
    }
}

// ---------------------------------------------------------------------------
__global__ void k_gather(const float* __restrict__ pos,
                         const float* __restrict__ chg,
                         float* __restrict__ out, int n) {
    int a = blockIdx.x * blockDim.x + threadIdx.x;
    if (a >= n) return;
    float wx[4], wy[4], wz[4];
    int ix[4], iy[4];
    int i2 = atom_stencil(pos, a, wx, wy, wz, ix, iy);
    float sum = 0.0f;
    int zlo = i2 - 1;
    if (zlo >= 0 && zlo <= 124) {
        int Q0 = zlo & ~3, off = zlo & 3;
        float q0[4] = {0,0,0,0}, q1[4] = {0,0,0,0};
        pad_quads(wz, off, q0, q1);
        #pragma unroll
        for (int i = 0; i < 4; i++) {
            float wi = wx[i];
            int ox = ix[i] << 14;
            #pragma unroll
            for (int j = 0; j < 4; j++) {
                const float* p = &d_rho[ox + (iy[j] << 7) + Q0];
                float4 v0 = __ldg((const float4*)p);
                float acc = v0.x*q0[0] + v0.y*q0[1] + v0.z*q0[2] + v0.w*q0[3];
                if (off) {
                    float4 v1 = __ldg((const float4*)(p + 4));
                    acc += v1.x*q1[0] + v1.y*q1[1] + v1.z*q1[2] + v1.w*q1[3];
                }
                sum += wi * wy[j] * acc;
            }
        }
    } else {
        int iz[4];
        #pragma unroll
        for (int s = 0; s < 4; s++) iz[s] = (zlo + s + 128) & 127;
        #pragma unroll
        for (int i = 0; i < 4; i++) {
            float wi = wx[i];
            int ox = ix[i] << 14;
            #pragma unroll
            for (int j = 0; j < 4; j++) {
                int oxy = ox + (iy[j] << 7);
                float acc = 0.0f;
                #pragma unroll
                for (int k = 0; k < 4; k++)
                    acc += wz[k] * d_rho[oxy + iz[k]];
                sum += wi * wy[j] * acc;
            }
        }
    }
    out[a] = sum - chg[a] * 0.7978845608028654f;
}

// ---------------------------------------------------------------------------
extern "C" void kernel_launch(void* const* d_in, const int* in_sizes, int n_in,
                              void* d_out, int out_size) {
    const float* cell = (const float*)d_in[0];
    const float* pos  = (const float*)d_in[1];
    const float* chg  = (const float*)d_in[2];
    float* out = (float*)d_out;
    int n = in_sizes[2];

    k_setup<<<1, 1>>>(cell);
    k_zero<<<2048, 256>>>();

    int ab = (n + 255) / 256;
    k_scatter<<<ab, 256>>>(pos, chg, n);

    k_fft_z_fwd<<<512, 256>>>();
    k_fft_y<0><<<520, 256>>>();
    k_fft_x_gmul<<<520, 256>>>();
    k_fft_y<1><<<520, 256>>>();
    k_fft_z_inv<<<512, 256>>>();

    k_gather<<<ab, 256>>>(pos, chg, out, n);
}

// round 4
// speedup vs baseline: 1.7547x; 1.0003x over previous
#include <cuda_runtime.h>
#include <math.h>

#define N3 (128*128*128)
#define NZH 65                       // Hermitian half length along z
#define KLINES (128*65)              // 8320 k-space lines for y/x passes

__device__ float2 d_kmesh[128*128*NZH];  // half-spectrum mesh (8.5 MB)
__device__ float  d_rho[N3];             // dense real mesh (8 MB)
__device__ float  d_minv[9];
__device__ float  d_brec[9];
__device__ float  d_invvol;

// ---------------------------------------------------------------------------
__global__ void k_setup(const float* __restrict__ cell) {
    float a = cell[0], b = cell[1], c = cell[2];
    float d = cell[3], e = cell[4], f = cell[5];
    float g = cell[6], h = cell[7], i = cell[8];
    float C00 =  (e*i - f*h), C01 = -(d*i - f*g), C02 =  (d*h - e*g);
    float C10 = -(b*i - c*h), C11 =  (a*i - c*g), C12 = -(a*h - b*g);
    float C20 =  (b*f - c*e), C21 = -(a*f - c*d), C22 =  (a*e - b*d);
    float det = a*C00 + b*C01 + c*C02;
    float idet = 1.0f / det;
    float inv[9];
    inv[0] = C00*idet; inv[1] = C10*idet; inv[2] = C20*idet;
    inv[3] = C01*idet; inv[4] = C11*idet; inv[5] = C21*idet;
    inv[6] = C02*idet; inv[7] = C12*idet; inv[8] = C22*idet;
    for (int t = 0; t < 9; t++) d_minv[t] = inv[t];
    const float TWO_PI = 6.283185307179586f;
    for (int r = 0; r < 3; r++)
        for (int s = 0; s < 3; s++)
            d_brec[r*3+s] = TWO_PI * inv[s*3+r];
    d_invvol = 1.0f / fabsf(det);
}

__global__ void k_zero() {
    int i = blockIdx.x * blockDim.x + threadIdx.x;   // 524288 float4s (8 MB)
    ((float4*)d_rho)[i] = make_float4(0.f, 0.f, 0.f, 0.f);
}

// ---------------------------------------------------------------------------
__device__ __forceinline__ float2 cadd(float2 a, float2 b){ return make_float2(a.x+b.x, a.y+b.y); }
__device__ __forceinline__ float2 csub(float2 a, float2 b){ return make_float2(a.x-b.x, a.y-b.y); }
__device__ __forceinline__ float2 cmul(float2 a, float2 w){ return make_float2(a.x*w.x-a.y*w.y, a.x*w.y+a.y*w.x); }

// ---------------------------------------------------------------------------
// Radix-4 Stockham stage over 8 lines of 128 (padded stride 129).
// 8 lines * 32 butterflies = 256 items = 1 per thread.
// ---------------------------------------------------------------------------
template<int CONJ, int S>
__device__ __forceinline__ void r4_stage(const float2* __restrict__ cur,
                                         float2* __restrict__ nxt,
                                         const float2* __restrict__ tw, int tid) {
    int c = tid >> 5, t = tid & 31;
    int off = c * 129;
    int q  = t & (S - 1);
    int sp = t - q;
    float2 a0 = cur[off + t];
    float2 a1 = cur[off + t + 32];
    float2 a2 = cur[off + t + 64];
    float2 a3 = cur[off + t + 96];
    float2 t02 = cadd(a0, a2), d02 = csub(a0, a2);
    float2 t13 = cadd(a1, a3), d13 = csub(a1, a3);
    float2 y0 = cadd(t02, t13);
    float2 y2 = csub(t02, t13);
    float2 jd;
    if (CONJ) jd = make_float2(-d13.y,  d13.x);
    else      jd = make_float2( d13.y, -d13.x);
    float2 y1 = cadd(d02, jd);
    float2 y3 = csub(d02, jd);
    float2 w1 = tw[sp], w2 = tw[2*sp], w3 = tw[3*sp];
    if (CONJ) { w1.y = -w1.y; w2.y = -w2.y; w3.y = -w3.y; }
    int o = off + t + 3*sp;
    nxt[o]       = y0;
    nxt[o + S]   = cmul(y1, w1);
    nxt[o + 2*S] = cmul(y2, w2);
    nxt[o + 3*S] = cmul(y3, w3);
}

template<int CONJ>
__device__ __forceinline__ void fft_r4_stages(float2* A, float2* B,
                                              const float2* tw, int tid) {
    r4_stage<CONJ, 1 >(A, B, tw, tid); __syncthreads();
    r4_stage<CONJ, 4 >(B, A, tw, tid); __syncthreads();
    r4_stage<CONJ, 16>(A, B, tw, tid); __syncthreads();
    // result (pre final radix-2) in B
}

// twiddle-free final radix-2: 8 lines * 64 = 512 items
__device__ __forceinline__ void r2_final_shared(const float2* __restrict__ src,
                                                float2* __restrict__ dst, int tid) {
    #pragma unroll
    for (int e = tid; e < 512; e += 256) {
        int c = e >> 6, t = e & 63;
        float2 a = src[c * 129 + t], b = src[c * 129 + t + 64];
        dst[c * 129 + t]      = cadd(a, b);
        dst[c * 129 + t + 64] = csub(a, b);
    }
}

__device__ __forceinline__ void init_tw(float2* tw, int tid) {
    if (tid < 128) {
        float s, c;
        sincospif((float)tid * (1.0f / 64.0f), &s, &c);
        tw[tid] = make_float2(c, -s);
    }
}

// ---------------------------------------------------------------------------
// z forward r2c (two-for-one): 16 real lines -> 16 half-spectrum lines / block
// 1024 blocks
// ---------------------------------------------------------------------------
__global__ void k_fft_z_fwd() {
    __shared__ float2 bufA[8 * 129];
    __shared__ float2 bufB[8 * 129];
    __shared__ float2 tw[128];
    int tid = threadIdx.x;
    int rl0 = blockIdx.x * 16;                 // first real line
    init_tw(tw, tid);
    const float* rp = d_rho + rl0 * 128;
    #pragma unroll
    for (int e = tid; e < 1024; e += 256) {
        int c = e >> 7, l = e & 127;
        bufA[c * 129 + l] = make_float2(rp[(2*c) * 128 + l], rp[(2*c+1) * 128 + l]);
    }
    __syncthreads();
    fft_r4_stages<0>(bufA, bufB, tw, tid);
    r2_final_shared(bufB, bufA, tid);
    __syncthreads();
    // unpack: real line (rl0+2c) -> A_k, (rl0+2c+1) -> B_k
    for (int e = tid; e < 16 * NZH; e += 256) {
        int rl = e / NZH, k = e - rl * NZH;
        int c = rl >> 1;
        float2 Ck = bufA[c * 129 + k];
        float2 Cm = bufA[c * 129 + ((128 - k) & 127)];
        float2 v;
        if ((rl & 1) == 0)
            v = make_float2(0.5f * (Ck.x + Cm.x), 0.5f * (Ck.y - Cm.y));
        else
            v = make_float2(0.5f * (Ck.y + Cm.y), -0.5f * (Ck.x - Cm.x));
        d_kmesh[(rl0 + rl) * NZH + k] = v;
    }
}

// ---------------------------------------------------------------------------
// z inverse c2r (two-for-one): 16 half-spectrum lines -> 16 real lines / block
// 1024 blocks
// ---------------------------------------------------------------------------
__global__ void k_fft_z_inv() {
    __shared__ float2 bufA[8 * 129];
    __shared__ float2 bufB[8 * 129];
    __shared__ float2 tw[128];
    int tid = threadIdx.x;
    int rl0 = blockIdx.x * 16;
    init_tw(tw, tid);
    for (int e = tid; e < 8 * NZH; e += 256) {
        int c = e / NZH, k = e - c * NZH;
        float2 A = d_kmesh[(rl0 + 2*c)   * NZH + k];
        float2 B = d_kmesh[(rl0 + 2*c+1) * NZH + k];
        bufA[c * 129 + k] = make_float2(A.x - B.y, A.y + B.x);
        if (k >= 1 && k <= 63)
            bufA[c * 129 + 128 - k] = make_float2(A.x + B.y, B.x - A.y);
    }
    __syncthreads();
    fft_r4_stages<1>(bufA, bufB, tw, tid);
    float* rp = d_rho + rl0 * 128;
    #pragma unroll
    for (int e = tid; e < 512; e += 256) {
        int c = e >> 6, l = e & 63;
        float2 a = bufB[c * 129 + l], b = bufB[c * 129 + l + 64];
        float2 su = cadd(a, b), df = csub(a, b);
        rp[(2*c) * 128 + l]        = su.x;
        rp[(2*c+1) * 128 + l]      = su.y;
        rp[(2*c) * 128 + l + 64]   = df.x;
        rp[(2*c+1) * 128 + l + 64] = df.y;
    }
}

// ---------------------------------------------------------------------------
// y pass: lines (x, kz) = L, elements at x*8320 + y*65 + kz.  1040 blocks.
// ---------------------------------------------------------------------------
template<int CONJ>
__global__ void k_fft_y() {
    __shared__ float2 bufA[8 * 129];
    __shared__ float2 bufB[8 * 129];
    __shared__ float2 tw[128];
    __shared__ int lineBase[8];
    int tid = threadIdx.x;
    init_tw(tw, tid);
    if (tid < 8) {
        int L = blockIdx.x * 8 + tid;
        int x = L / NZH, kz = L - x * NZH;
        lineBase[tid] = x * (128 * NZH) + kz;
    }
    __syncthreads();
    #pragma unroll
    for (int e = tid; e < 1024; e += 256) {
        int c = e & 7, l = e >> 3;
        bufA[c * 129 + l] = d_kmesh[lineBase[c] + l * NZH];
    }
    __syncthreads();
    fft_r4_stages<CONJ>(bufA, bufB, tw, tid);
    #pragma unroll
    for (int e = tid; e < 512; e += 256) {
        int c = e & 7, l = e >> 3;
        float2 a = bufB[c * 129 + l], b = bufB[c * 129 + l + 64];
        d_kmesh[lineBase[c] + l * NZH]        = cadd(a, b);
        d_kmesh[lineBase[c] + (l + 64) * NZH] = csub(a, b);
    }
}

// ---------------------------------------------------------------------------
// Fused x pass: fwd FFT along x, G(k)/V multiply, inv FFT along x. 1040 blocks.
// lines L = y*65 + kz, elements at x*8320 + L.
// ---------------------------------------------------------------------------
__global__ void k_fft_x_gmul() {
    __shared__ float2 bufA[8 * 129];
    __shared__ float2 bufB[8 * 129];
    __shared__ float2 tw[128];
    __shared__ float mjv[8], mkv[8];
    int tid = threadIdx.x;
    int L0 = blockIdx.x * 8;
    init_tw(tw, tid);
    if (tid < 8) {
        int L = L0 + tid;
        int y = L / NZH, kz = L - y * NZH;
        mjv[tid] = (float)(y - ((y >= 64) ? 128 : 0));
        mkv[tid] = (float)kz;
    }
    __syncthreads();
    #pragma unroll
    for (int e = tid; e < 1024; e += 256) {
        int c = e & 7, l = e >> 3;
        bufA[c * 129 + l] = d_kmesh[L0 + c + l * KLINES];
    }
    __syncthreads();
    fft_r4_stages<0>(bufA, bufB, tw, tid);
    r2_final_shared(bufB, bufA, tid);
    __syncthreads();
    // G(k)/V
    float b0x = d_brec[0], b0y = d_brec[1], b0z = d_brec[2];
    float b1x = d_brec[3], b1y = d_brec[4], b1z = d_brec[5];
    float b2x = d_brec[6], b2y = d_brec[7], b2z = d_brec[8];
    float ivol = d_invvol;
    #pragma unroll
    for (int e = tid; e < 1024; e += 256) {
        int c = e >> 7, xk = e & 127;
        float mi = (float)(xk - ((xk >= 64) ? 128 : 0));
        float mj = mjv[c], mk = mkv[c];
        float kx = mi * b0x + mj * b1x + mk * b2x;
        float ky = mi * b0y + mj * b1y + mk * b2y;
        float kz = mi * b0z + mj * b1z + mk * b2z;
        float ksq = kx * kx + ky * ky + kz * kz;
        float g = 0.0f;
        if (ksq != 0.0f)
            g = 12.566370614359172f / ksq * expf(-0.5f * ksq) * ivol;
        float2 v = bufA[c * 129 + xk];
        v.x *= g; v.y *= g;
        bufA[c * 129 + xk] = v;
    }
    __syncthreads();
    fft_r4_stages<1>(bufA, bufB, tw, tid);
    #pragma unroll
    for (int e = tid; e < 512; e += 256) {
        int c = e & 7, l = e >> 3;
        float2 a = bufB[c * 129 + l], b = bufB[c * 129 + l + 64];
        d_kmesh[L0 + c + l * KLINES]        = cadd(a, b);
        d_kmesh[L0 + c + (l + 64) * KLINES] = csub(a, b);
    }
}

// ---------------------------------------------------------------------------
// spline weights + stencil
// ---------------------------------------------------------------------------
__device__ __forceinline__ void spline_w4(float x, float* w) {
    float x2 = x * x, x3 = x2 * x;
    const float s = 1.0f / 48.0f;
    w[0] = ( 1.0f -  6.0f*x + 12.0f*x2 -  8.0f*x3) * s;
    w[1] = (23.0f - 30.0f*x - 12.0f*x2 + 24.0f*x3) * s;
    w[2] = (23.0f + 30.0f*x - 12.0f*x2 - 24.0f*x3) * s;
    w[3] = ( 1.0f +  6.0f*x + 12.0f*x2 +  8.0f*x3) * s;
}

__device__ __forceinline__ int atom_stencil(
    const float* __restrict__ pos, int a,
    float* wx, float* wy, float* wz, int* ix, int* iy)
{
    float p0 = pos[3*a], p1 = pos[3*a+1], p2 = pos[3*a+2];
    float r0 = (p0*d_minv[0] + p1*d_minv[3] + p2*d_minv[6]) * 128.0f;
    float r1 = (p0*d_minv[1] + p1*d_minv[4] + p2*d_minv[7]) * 128.0f;
    float r2 = (p0*d_minv[2] + p1*d_minv[5] + p2*d_minv[8]) * 128.0f;
    int i0 = __float2int_rd(r0);
    int i1 = __float2int_rd(r1);
    int i2 = __float2int_rd(r2);
    spline_w4(r0 - (float)i0 - 0.5f, wx);
    spline_w4(r1 - (float)i1 - 0.5f, wy);
    spline_w4(r2 - (float)i2 - 0.5f, wz);
    #pragma unroll
    for (int s = 0; s < 4; s++) {
        ix[s] = (i0 + s - 1 + 128) & 127;
        iy[s] = (i1 + s - 1 + 128) & 127;
    }
    return i2;
}

__device__ __forceinline__ void pad_quads(const float* wz, int off,
                                          float* q0, float* q1) {
    switch (off) {
    case 0: q0[0]=wz[0]; q0[1]=wz[1]; q0[2]=wz[2]; q0[3]=wz[3]; break;
    case 1: q0[1]=wz[0]; q0[2]=wz[1]; q0[3]=wz[2]; q1[0]=wz[3]; break;
    case 2: q0[2]=wz[0]; q0[3]=wz[1]; q1[0]=wz[2]; q1[1]=wz[3]; break;
    default:q0[3]=wz[0]; q1[0]=wz[1]; q1[1]=wz[2]; q1[2]=wz[3]; break;
    }
}

__device__ __forceinline__ void red4(float* p, float a, float b, float c, float d) {
    asm volatile("red.global.add.v4.f32 [%0], {%1, %2, %3, %4};"
                 :: "l"(p), "f"(a), "f"(b), "f"(c), "f"(d) : "memory");
}
__device__ __forceinline__ void red2(float* p, float a, float b) {
    asm volatile("red.global.add.v2.f32 [%0], {%1, %2};"
                 :: "l"(p), "f"(a), "f"(b) : "memory");
}
__device__ __forceinline__ void red1(float* p, float a) {
    asm volatile("red.global.add.f32 [%0], %1;"
                 :: "l"(p), "f"(a) : "memory");
}

// ---------------------------------------------------------------------------
__global__ void k_scatter(const float* __restrict__ pos,
                          const float* __restrict__ chg, int n) {
    int a = blockIdx.x * blockDim.x + threadIdx.x;
    if (a >= n) return;
    float wx[4], wy[4], wz[4];
    int ix[4], iy[4];
    int i2 = atom_stencil(pos, a, wx, wy, wz, ix, iy);
    float c = chg[a];
    int zlo = i2 - 1;
    if (zlo >= 0 && zlo <= 124) {
        int Q0 = zlo & ~3, off = zlo & 3;
        #pragma unroll
        for (int i = 0; i < 4; i++) {
            float cwi = c * wx[i];
            int ox = ix[i] << 14;
            #pragma unroll
            for (int j = 0; j < 4; j++) {
                float s = cwi * wy[j];
                float* p = &d_rho[ox + (iy[j] << 7) + Q0];
                switch (off) {
                case 0:
                    red4(p, s*wz[0], s*wz[1], s*wz[2], s*wz[3]);
                    break;
                case 1:
                    red4(p, 0.0f, s*wz[0], s*wz[1], s*wz[2]);
                    red1(p + 4, s*wz[3]);
                    break;
                case 2:
                    red2(p + 2, s*wz[0], s*wz[1]);
                    red2(p + 4, s*wz[2], s*wz[3]);
                    break;
                default:
                    red1(p + 3, s*wz[0]);
                    red4(p + 4, s*wz[1], s*wz[2], s*wz[3], 0.0f);
                    break;
                }
            }
        }
    } else {
        int iz[4];
        #pragma unroll
        for (int s = 0; s < 4; s++) iz[s] = (zlo + s + 128) & 127;
        #pragma unroll
        for (int i = 0; i < 4; i++) {
            float cwi = c * wx[i];
            int ox = ix[i] << 14;
            #pragma unroll
            for (int j = 0; j < 4; j++) {
                float cwij = cwi * wy[j];
                int oxy = ox + (iy[j] << 7);
                #pragma unroll
                for (int k = 0; k < 4; k++)
                    red1(&d_rho[oxy + iz[k]], cwij * wz[k]);
            }
        }
    }
}

// ---------------------------------------------------------------------------
__global__ void k_gather(const float* __restrict__ pos,
                         const float* __restrict__ chg,
                         float* __restrict__ out, int n) {
    int a = blockIdx.x * blockDim.x + threadIdx.x;
    if (a >= n) return;
    float wx[4], wy[4], wz[4];
    int ix[4], iy[4];
    int i2 = atom_stencil(pos, a, wx, wy, wz, ix, iy);
    float sum = 0.0f;
    int zlo = i2 - 1;
    if (zlo >= 0 && zlo <= 124) {
        int Q0 = zlo & ~3, off = zlo & 3;
        float q0[4] = {0,0,0,0}, q1[4] = {0,0,0,0};
        pad_quads(wz, off, q0, q1);
        #pragma unroll
        for (int i = 0; i < 4; i++) {
            float wi = wx[i];
            int ox = ix[i] << 14;
            #pragma unroll
            for (int j = 0; j < 4; j++) {
                const float* p = &d_rho[ox + (iy[j] << 7) + Q0];
                float4 v0 = __ldg((const float4*)p);
                float acc = v0.x*q0[0] + v0.y*q0[1] + v0.z*q0[2] + v0.w*q0[3];
                if (off) {
                    float4 v1 = __ldg((const float4*)(p + 4));
                    acc += v1.x*q1[0] + v1.y*q1[1] + v1.z*q1[2] + v1.w*q1[3];
                }
                sum += wi * wy[j] * acc;
            }
        }
    } else {
        int iz[4];
        #pragma unroll
        for (int s = 0; s < 4; s++) iz[s] = (zlo + s + 128) & 127;
        #pragma unroll
        for (int i = 0; i < 4; i++) {
            float wi = wx[i];
            int ox = ix[i] << 14;
            #pragma unroll
            for (int j = 0; j < 4; j++) {
                int oxy = ox + (iy[j] << 7);
                float acc = 0.0f;
                #pragma unroll
                for (int k = 0; k < 4; k++)
                    acc += wz[k] * d_rho[oxy + iz[k]];
                sum += wi * wy[j] * acc;
            }
        }
    }
    out[a] = sum - chg[a] * 0.7978845608028654f;
}

// ---------------------------------------------------------------------------
extern "C" void kernel_launch(void* const* d_in, const int* in_sizes, int n_in,
                              void* d_out, int out_size) {
    const float* cell = (const float*)d_in[0];
    const float* pos  = (const float*)d_in[1];
    const float* chg  = (const float*)d_in[2];
    float* out = (float*)d_out;
    int n = in_sizes[2];

    k_setup<<<1, 1>>>(cell);
    k_zero<<<2048, 256>>>();

    int ab = (n + 255) / 256;
    k_scatter<<<ab, 256>>>(pos, chg, n);

    k_fft_z_fwd<<<1024, 256>>>();
    k_fft_y<0><<<1040, 256>>>();
    k_fft_x_gmul<<<1040, 256>>>();
    k_fft_y<1><<<1040, 256>>>();
    k_fft_z_inv<<<1024, 256>>>();

    k_gather<<<ab, 256>>>(pos, chg, out, n);
}